// round 10
// baseline (speedup 1.0000x reference)
#include <cuda_runtime.h>

// Problem shape (fixed by reference)
#define Bdim  128
#define Tdim  1024
#define Idim  64
#define Hdim  512
#define BBdim 128
#define Odim  2

#define NCTA 128   // one CTA per 4 hidden units; also CTA j <-> batch j for phys head
#define NTHR 512   // 16 warps

#define BRS   132          // chunk buffer row stride (33 float4s, odd -> conflict-free)
#define CBUF  (128 * BRS)  // one chunk buffer: 16896 floats
#define PST   20           // partial row stride (5 float4s, 16B aligned, conflict-free)
#define PBLK  (128 * PST)  // one partial block: 2560 floats (8 blocks = 20480 <= 33792)

// Cross-CTA state (persistent kernel; no allocations allowed)
__device__ float g_h[Bdim * Hdim];      // h_{t-1} / h_t
__device__ float g_hl[Bdim * Hdim];     // h_lstm at current step
__device__ float g_f[Bdim * BBdim];     // backbone activations
__device__ unsigned g_bar_count;
__device__ volatile unsigned g_bar_flag;

__device__ __forceinline__ float sigm(float v) { return 1.0f / (1.0f + expf(-v)); }

// Proven atomic barrier, split into arrive / wait (R8).
__device__ __forceinline__ void bar_arrive(unsigned &expect) {
    __syncthreads();
    expect += 1u;
    if (threadIdx.x == 0) {
        __threadfence();
        if (atomicAdd(&g_bar_count, 1u) == NCTA - 1) {
            g_bar_count = 0;
            __threadfence();
            g_bar_flag = expect;
        }
    }
}
__device__ __forceinline__ void bar_wait(unsigned expect) {
    if (threadIdx.x == 0) {
        while (g_bar_flag != expect) { }
    }
    __syncthreads();
}

// 16 gate-FMAs for TWO batches against one weight row: 4 LDS.128 + 16 FFMA2.
__device__ __forceinline__ void fma16x2_dual(unsigned long long aL[8],
                                             unsigned long long aH[8],
                                             const float* wrow, float vL, float vH) {
    unsigned long long vL2, vH2;
    asm("mov.b64 %0, {%1, %1};" : "=l"(vL2) : "r"(__float_as_uint(vL)));
    asm("mov.b64 %0, {%1, %1};" : "=l"(vH2) : "r"(__float_as_uint(vH)));
    #pragma unroll
    for (int g = 0; g < 4; ++g) {
        ulonglong2 w2 = *(const ulonglong2*)(wrow + g * 4);
        asm("fma.rn.f32x2 %0, %1, %2, %0;" : "+l"(aL[2*g])   : "l"(w2.x), "l"(vL2));
        asm("fma.rn.f32x2 %0, %1, %2, %0;" : "+l"(aH[2*g])   : "l"(w2.x), "l"(vH2));
        asm("fma.rn.f32x2 %0, %1, %2, %0;" : "+l"(aL[2*g+1]) : "l"(w2.y), "l"(vL2));
        asm("fma.rn.f32x2 %0, %1, %2, %0;" : "+l"(aH[2*g+1]) : "l"(w2.y), "l"(vH2));
    }
}

// One 4-k slab (one float4 of activations per batch) of a 16-gate GEMM.
__device__ __forceinline__ void gemm_4k(unsigned long long aL[8],
                                        unsigned long long aH[8],
                                        const float* rl, const float* rh,
                                        const float* wpc) {
    float4 al = *(const float4*)rl;
    float4 ah = *(const float4*)rh;
    fma16x2_dual(aL, aH, wpc +  0, al.x, ah.x);
    fma16x2_dual(aL, aH, wpc + 16, al.y, ah.y);
    fma16x2_dual(aL, aH, wpc + 32, al.z, ah.z);
    fma16x2_dual(aL, aH, wpc + 48, al.w, ah.w);
}

__device__ __forceinline__ float pk_lo(unsigned long long p) {
    return __uint_as_float((unsigned)(p & 0xffffffffu));
}
__device__ __forceinline__ float pk_hi(unsigned long long p) {
    return __uint_as_float((unsigned)(p >> 32));
}

// Vector dump of 16 packed partials (both batches) at stride-PST layout.
__device__ __forceinline__ void dump_partials(float* base, int oct, int blo, int bhi,
                                              const unsigned long long aL[8],
                                              const unsigned long long aH[8]) {
    float* dl = base + oct * PBLK + blo * PST;
    float* dh = base + oct * PBLK + bhi * PST;
    #pragma unroll
    for (int g = 0; g < 4; ++g) {
        *(float4*)(dl + g * 4) = make_float4(pk_lo(aL[2*g]), pk_hi(aL[2*g]),
                                             pk_lo(aL[2*g+1]), pk_hi(aL[2*g+1]));
        *(float4*)(dh + g * 4) = make_float4(pk_lo(aH[2*g]), pk_hi(aH[2*g]),
                                             pk_lo(aH[2*g+1]), pk_hi(aH[2*g+1]));
    }
}

// Vector gather+sum of 8 partial blocks for batch b into z[16].
__device__ __forceinline__ void sum_partials(float z[16], const float* base, int b,
                                             const float* bias) {
    #pragma unroll
    for (int q = 0; q < 16; q++) z[q] = bias[q];
    #pragma unroll
    for (int p = 0; p < 8; p++) {
        const float* s = base + p * PBLK + b * PST;
        #pragma unroll
        for (int g = 0; g < 4; ++g) {
            float4 v = *(const float4*)(s + g * 4);
            z[4*g]   += v.x;  z[4*g+1] += v.y;
            z[4*g+2] += v.z;  z[4*g+3] += v.w;
        }
    }
}

__global__ __launch_bounds__(NTHR, 1)
void cfc_kernel(const float* __restrict__ x,
                const float* __restrict__ lstm_Wi, const float* __restrict__ lstm_bi,
                const float* __restrict__ lstm_Wh,
                const float* __restrict__ bb_W,  const float* __restrict__ bb_b,
                const float* __restrict__ ff1_W, const float* __restrict__ ff1_b,
                const float* __restrict__ ff2_W, const float* __restrict__ ff2_b,
                const float* __restrict__ ta_W,  const float* __restrict__ ta_b,
                const float* __restrict__ tb_W,  const float* __restrict__ tb_b,
                const float* __restrict__ head_W, const float* __restrict__ head_b,
                float* __restrict__ out)
{
    extern __shared__ float sm[];
    float* wA2  = sm;                    // [576][16] gate weights, k-major layout
    float* wB   = wA2 + 576 * 16;        // [16][576] bb_W row block (row-major)
    float* wC2  = wB + 16 * 576;         // [128][16] ff1/ff2/ta/tb, k-major
    float* hW   = wC2 + 128 * 16;        // [2][512] head
    float* bA   = hW + 2 * 512;          // 16
    float* bB   = bA + 16;               // 16
    float* bC   = bB + 16;               // 16
    float* hb   = bC + 16;               // 16 (2 used)
    float* buf  = hb + 16;               // 2*CBUF = 33792 floats, multi-purpose

    const int tid = threadIdx.x;
    const int j   = blockIdx.x;          // owns hidden units 4j..4j+3; batch j for head
    const int b2  = tid & 63;            // batch pair: handles b2 and b2+64
    const int oct = tid >> 6;            // k-split 0..7 (uniform per warp)
    const int blo = b2, bhi = b2 + 64;
    const int bb0 = (j >> 3) * 8;        // phase-B batch block
    const int jj0 = (j & 7) * 16;        // phase-B bb_W row block

    // ---- One-time: resident weights into smem ----
    for (int idx = tid; idx < 576 * 16; idx += NTHR) {
        int k = idx >> 4, q = idx & 15;
        int grow = (q >> 2) * Hdim + 4 * j + (q & 3);   // gate g=q>>2, unit u=q&3
        wA2[idx] = (k < Idim) ? lstm_Wi[grow * Idim + k]
                              : lstm_Wh[grow * Hdim + (k - Idim)];
    }
    for (int idx = tid; idx < 16 * 576; idx += NTHR) {
        int r = idx / 576, k = idx - r * 576;
        wB[idx] = bb_W[(jj0 + r) * 576 + k];
    }
    for (int idx = tid; idx < 128 * 16; idx += NTHR) {
        int k = idx >> 4, r = idx & 15;
        const float* Wm = (r < 4) ? ff1_W : (r < 8) ? ff2_W : (r < 12) ? ta_W : tb_W;
        wC2[idx] = Wm[(4 * j + (r & 3)) * BBdim + k];
    }
    for (int idx = tid; idx < 2 * Hdim; idx += NTHR) hW[idx] = head_W[idx];
    if (tid < 16) {
        bA[tid] = lstm_bi[(tid >> 2) * Hdim + 4 * j + (tid & 3)];
        bB[tid] = bb_b[jj0 + tid];
        const float* bm = (tid < 4) ? ff1_b : (tid < 8) ? ff2_b : (tid < 12) ? ta_b : tb_b;
        bC[tid] = bm[4 * j + (tid & 3)];
    }
    if (tid < 2) hb[tid] = head_b[tid];
    __syncthreads();

    unsigned expect = 0;
    if (tid == 0) expect = g_bar_flag;   // race-free epoch base

    float cReg[4] = {0.f, 0.f, 0.f, 0.f};  // cell state for batch==tid (tid<128)

    for (int t = 0; t < Tdim; ++t) {
        // ============ Phase A: z = [x_t,h] @ W.T, LSTM update ============
        unsigned long long aLo[8], aHi[8];
        #pragma unroll
        for (int p = 0; p < 8; p++) { aLo[p] = 0ull; aHi[p] = 0ull; }

        // --- bar3(t-1) overlap window: stage x chunk (64 cols), compute 1st half ---
        {
            float4 st[4];
            #pragma unroll
            for (int r4 = 0; r4 < 4; r4++) {
                int idx4 = tid + NTHR * r4;
                int row = idx4 >> 4, c4 = idx4 & 15;
                st[r4] = *(const float4*)(x + (long)row * (Tdim * Idim) + t * Idim + c4 * 4);
            }
            #pragma unroll
            for (int r4 = 0; r4 < 4; r4++) {
                int idx4 = tid + NTHR * r4;
                int row = idx4 >> 4, c4 = idx4 & 15;
                *(float4*)(buf + row * BRS + c4 * 4) = st[r4];
            }
        }
        __syncthreads();
        const float* rl0 = buf + blo * BRS + oct * 8;
        const float* rh0 = buf + bhi * BRS + oct * 8;
        gemm_4k(aLo, aHi, rl0, rh0, wA2 + (oct * 8) * 16);

        bar_wait(expect);    // bar3(t-1): h_{t-1} ready (no-op at t=0)

        if (t > 0) {
            float* nb1 = buf + CBUF;         // chunk 1 buffer
            {   // prefetch h chunk 1 first half (g_h cols 0..63) around x 2nd half
                float4 p0[4];
                #pragma unroll
                for (int r4 = 0; r4 < 4; r4++) {
                    int idx4 = tid + NTHR * r4;
                    int row = idx4 >> 4, c4 = idx4 & 15;
                    p0[r4] = __ldcg((const float4*)(g_h + row * Hdim + c4 * 4));
                }
                gemm_4k(aLo, aHi, rl0 + 4, rh0 + 4, wA2 + (oct * 8 + 4) * 16);
                #pragma unroll
                for (int r4 = 0; r4 < 4; r4++) {
                    int idx4 = tid + NTHR * r4;
                    int row = idx4 >> 4, c4 = idx4 & 15;
                    *(float4*)(nb1 + row * BRS + c4 * 4) = p0[r4];
                }
                float4 p1[4];                // second half (cols 64..127)
                #pragma unroll
                for (int r4 = 0; r4 < 4; r4++) {
                    int idx4 = tid + NTHR * r4;
                    int row = idx4 >> 4, c4 = idx4 & 15;
                    p1[r4] = __ldcg((const float4*)(g_h + row * Hdim + 64 + c4 * 4));
                }
                #pragma unroll
                for (int r4 = 0; r4 < 4; r4++) {
                    int idx4 = tid + NTHR * r4;
                    int row = idx4 >> 4, c4 = idx4 & 15;
                    *(float4*)(nb1 + row * BRS + 64 + c4 * 4) = p1[r4];
                }
            }
            __syncthreads();

            // h chunks: 4 chunks of 128 cols; chunk c holds g_h cols [(c-1)*128, c*128)
            for (int c = 1; c <= 4; ++c) {
                const float* cb = buf + ((c & 1) ? CBUF : 0);
                const float* rl = cb + blo * BRS + oct * 16;
                const float* rh = cb + bhi * BRS + oct * 16;
                const float* wpc = wA2 + (64 + (c - 1) * 128 + oct * 16) * 16;
                if (c < 4) {
                    float* nb = buf + (((c + 1) & 1) ? CBUF : 0);
                    float4 q0[4];            // next chunk, cols c*128 .. +64
                    #pragma unroll
                    for (int r4 = 0; r4 < 4; r4++) {
                        int idx4 = tid + NTHR * r4;
                        int row = idx4 >> 4, c4 = idx4 & 15;
                        q0[r4] = __ldcg((const float4*)(g_h + row * Hdim + c * 128 + c4 * 4));
                    }
                    gemm_4k(aLo, aHi, rl,     rh,     wpc);
                    gemm_4k(aLo, aHi, rl + 4, rh + 4, wpc + 64);
                    #pragma unroll
                    for (int r4 = 0; r4 < 4; r4++) {
                        int idx4 = tid + NTHR * r4;
                        int row = idx4 >> 4, c4 = idx4 & 15;
                        *(float4*)(nb + row * BRS + c4 * 4) = q0[r4];
                    }
                    float4 q1[4];            // next chunk, cols c*128+64 .. +128
                    #pragma unroll
                    for (int r4 = 0; r4 < 4; r4++) {
                        int idx4 = tid + NTHR * r4;
                        int row = idx4 >> 4, c4 = idx4 & 15;
                        q1[r4] = __ldcg((const float4*)(g_h + row * Hdim + c * 128 + 64 + c4 * 4));
                    }
                    gemm_4k(aLo, aHi, rl + 8,  rh + 8,  wpc + 128);
                    gemm_4k(aLo, aHi, rl + 12, rh + 12, wpc + 192);
                    #pragma unroll
                    for (int r4 = 0; r4 < 4; r4++) {
                        int idx4 = tid + NTHR * r4;
                        int row = idx4 >> 4, c4 = idx4 & 15;
                        *(float4*)(nb + row * BRS + 64 + c4 * 4) = q1[r4];
                    }
                } else {
                    gemm_4k(aLo, aHi, rl,      rh,      wpc);
                    gemm_4k(aLo, aHi, rl + 4,  rh + 4,  wpc + 64);
                    gemm_4k(aLo, aHi, rl + 8,  rh + 8,  wpc + 128);
                    gemm_4k(aLo, aHi, rl + 12, rh + 12, wpc + 192);
                }
                __syncthreads();
            }
        } else {
            gemm_4k(aLo, aHi, rl0 + 4, rh0 + 4, wA2 + (oct * 8 + 4) * 16);
            __syncthreads();             // protect buf before partial writes
        }

        // 8-way k-partial dump (vectorized, stride-PST)
        dump_partials(buf, oct, blo, bhi, aLo, aHi);
        __syncthreads();
        if (tid < 128) {                 // thread tid finalizes batch tid
            float z[16];
            sum_partials(z, buf, tid, bA);
            float hl[4];
            #pragma unroll
            for (int u = 0; u < 4; u++) {
                // z rows: [0..3]=i_, [4..7]=ig, [8..11]=fg, [12..15]=og
                float cn = cReg[u] * sigm(z[8 + u] + 1.0f) + tanhf(z[u]) * sigm(z[4 + u]);
                cReg[u] = cn;
                hl[u] = tanhf(cn) * sigm(z[12 + u]);
            }
            *(float4*)(g_hl + tid * Hdim + 4 * j) = make_float4(hl[0], hl[1], hl[2], hl[3]);
        }

        bar_arrive(expect);  // bar1: h_lstm posted

        // --- bar1 overlap window: phys head (t-1) + Phase-B x staging ---
        if (t > 0 && tid < 64) {
            int o = tid >> 5, l = tid & 31;
            float s = 0.f;
            for (int n = l; n < Hdim; n += 32)
                s += __ldcg(g_h + j * Hdim + n) * hW[o * Hdim + n];
            #pragma unroll
            for (int off = 16; off; off >>= 1) s += __shfl_down_sync(0xffffffffu, s, off);
            if (l == 0) out[((long)j * Tdim + (t - 1)) * Odim + o] = s + hb[o];
        }
        if (tid >= 128 && tid < 256) {   // B rows' x columns (no h_lstm dependency)
            int idx = tid - 128;
            int row = idx >> 4, col = (idx & 15) * 4;
            *(float4*)(buf + row * 576 + col) =
                *(const float4*)(x + (long)(bb0 + row) * (Tdim * Idim) + t * Idim + col);
        }

        bar_wait(expect);    // bar1: h_lstm ready

        // ============ Phase B: f = lecun_tanh([x_t,h_lstm] @ bbW.T + b) ============
        #pragma unroll
        for (int r2 = 0; r2 < 2; ++r2) {     // stage h_lstm columns (8 rows x 512 cols)
            int idx4 = tid + NTHR * r2;
            int row = idx4 >> 7, c4 = idx4 & 127;
            int col = 64 + c4 * 4;
            *(float4*)(buf + row * 576 + col) =
                __ldcg((const float4*)(g_hl + (bb0 + row) * Hdim + col - 64));
        }
        __syncthreads();
        float* bsc = buf + CBUF;         // 256-float reduction scratch
        {
            int w  = tid >> 5, l = tid & 31;
            int lb = w >> 1, kh = w & 1;     // local batch 0..7, k-half 0/1
            float a[16];
            #pragma unroll
            for (int r = 0; r < 16; r++) a[r] = 0.f;
            const float* xr = buf + lb * 576 + kh * 288;
            const float* wb = wB + kh * 288;
            for (int it = 0; it < 9; ++it) {
                int kk = it * 32 + l;
                float v = xr[kk];
                #pragma unroll
                for (int r = 0; r < 16; r++) a[r] = fmaf(v, wb[r * 576 + kk], a[r]);
            }
            #pragma unroll
            for (int r = 0; r < 16; r++) {
                #pragma unroll
                for (int off = 16; off; off >>= 1)
                    a[r] += __shfl_down_sync(0xffffffffu, a[r], off);
            }
            if (l == 0) {
                #pragma unroll
                for (int r = 0; r < 16; r++) bsc[(lb * 2 + kh) * 16 + r] = a[r];
            }
        }
        __syncthreads();
        if (tid < 128) {
            int lb = tid >> 4, r = tid & 15;
            float v = bsc[lb * 32 + r] + bsc[lb * 32 + 16 + r] + bB[r];
            g_f[(bb0 + lb) * BBdim + jj0 + r] = 1.7159f * tanhf(0.666f * v);
        }

        bar_arrive(expect);  // bar2: f posted
        bar_wait(expect);    // bar2: f ready

        // ============ Phase C: ff1/ff2/ta/tb, h_new ============
        #pragma unroll
        for (int r8 = 0; r8 < 8; ++r8) {     // stage full f (128x128), stride BRS
            int idx4 = tid + NTHR * r8;
            int row = idx4 >> 5, c4 = idx4 & 31;
            float4 v = __ldcg((const float4*)(g_f + row * BBdim + c4 * 4));
            *(float4*)(buf + row * BRS + c4 * 4) = v;
        }
        __syncthreads();
        unsigned long long cLo[8], cHi[8];
        #pragma unroll
        for (int p = 0; p < 8; p++) { cLo[p] = 0ull; cHi[p] = 0ull; }
        {
            const float* rl = buf + blo * BRS + oct * 16;
            const float* rh = buf + bhi * BRS + oct * 16;
            const float* wpc = wC2 + (oct * 16) * 16;
            #pragma unroll
            for (int s = 0; s < 4; ++s)
                gemm_4k(cLo, cHi, rl + s * 4, rh + s * 4, wpc + s * 64);
        }
        __syncthreads();
        dump_partials(buf, oct, blo, bhi, cLo, cHi);
        __syncthreads();
        if (tid < 128) {
            float z[16];
            sum_partials(z, buf, tid, bC);
            float hn[4];
            #pragma unroll
            for (int u = 0; u < 4; u++) {
                float f1 = tanhf(z[u]);                  // ff1
                float f2 = tanhf(z[4 + u]);              // ff2
                float ti = sigm(z[8 + u] + z[12 + u]);   // sigmoid(ta*1 + tb)
                hn[u] = f1 * (1.f - ti) + ti * f2;
            }
            *(float4*)(g_h + tid * Hdim + 4 * j) = make_float4(hn[0], hn[1], hn[2], hn[3]);
        }

        bar_arrive(expect);  // bar3: h_t posted (waited at top of next iteration)
    }

    bar_wait(expect);        // final bar3: h_{T-1} ready everywhere

    // ---- Epilogue: phys for t = T-1, and last_h ----
    if (tid < 64) {
        int o = tid >> 5, l = tid & 31;
        float s = 0.f;
        for (int n = l; n < Hdim; n += 32)
            s += __ldcg(g_h + j * Hdim + n) * hW[o * Hdim + n];
        #pragma unroll
        for (int off = 16; off; off >>= 1) s += __shfl_down_sync(0xffffffffu, s, off);
        if (l == 0) out[((long)j * Tdim + (Tdim - 1)) * Odim + o] = s + hb[o];
    }
    float* out_lh = out + (long)Bdim * Tdim * Odim;
    for (int i4 = tid; i4 < Hdim / 4; i4 += NTHR) {
        float4 v = __ldcg((const float4*)(g_h + j * Hdim + i4 * 4));
        *(float4*)(out_lh + j * Hdim + i4 * 4) = v;
    }
}

extern "C" void kernel_launch(void* const* d_in, const int* in_sizes, int n_in,
                              void* d_out, int out_size) {
    (void)in_sizes; (void)n_in; (void)out_size;
    const int SMEM_BYTES = (576 * 16 + 16 * 576 + 128 * 16 + 2 * 512 + 64
                            + 2 * CBUF) * 4;   // 221,440 B
    cudaFuncSetAttribute(cfc_kernel, cudaFuncAttributeMaxDynamicSharedMemorySize, SMEM_BYTES);
    cfc_kernel<<<NCTA, NTHR, SMEM_BYTES>>>(
        (const float*)d_in[0],  (const float*)d_in[1],  (const float*)d_in[2],
        (const float*)d_in[3],  (const float*)d_in[4],  (const float*)d_in[5],
        (const float*)d_in[6],  (const float*)d_in[7],  (const float*)d_in[8],
        (const float*)d_in[9],  (const float*)d_in[10], (const float*)d_in[11],
        (const float*)d_in[12], (const float*)d_in[13], (const float*)d_in[14],
        (const float*)d_in[15], (float*)d_out);
}

// round 12
// speedup vs baseline: 1.0272x; 1.0272x over previous
#include <cuda_runtime.h>

// Problem shape (fixed by reference)
#define Bdim  128
#define Tdim  1024
#define Idim  64
#define Hdim  512
#define BBdim 128
#define Odim  2

#define NCTA 128   // one CTA per 4 hidden units; also CTA j <-> batch j for phys head
#define NTHR 512   // 16 warps

#define RS    68           // buffer row stride (17 float4s -> conflict-free LDS.128)
#define PST   20           // partial row stride (5 float4s, conflict-free vector r/w)
#define PBLK  (128 * PST)  // one partial block: 2560 floats; 8 blocks = 20480
#define BUFFL 20480        // buffer region floats (covers 2*128*RS=17408 and partials)

// Cross-CTA state (persistent kernel; no allocations allowed)
__device__ float g_h[Bdim * Hdim];      // h_{t-1} / h_t
__device__ float g_hl[Bdim * Hdim];     // h_lstm at current step
__device__ float g_f[Bdim * BBdim];     // backbone activations
__device__ unsigned g_bar_count;
__device__ volatile unsigned g_bar_flag;

__device__ __forceinline__ float sigm(float v) { return 1.0f / (1.0f + expf(-v)); }

// Proven atomic barrier, split into arrive / wait (R8).
__device__ __forceinline__ void bar_arrive(unsigned &expect) {
    __syncthreads();
    expect += 1u;
    if (threadIdx.x == 0) {
        __threadfence();
        if (atomicAdd(&g_bar_count, 1u) == NCTA - 1) {
            g_bar_count = 0;
            __threadfence();
            g_bar_flag = expect;
        }
    }
}
__device__ __forceinline__ void bar_wait(unsigned expect) {
    if (threadIdx.x == 0) {
        while (g_bar_flag != expect) { }
    }
    __syncthreads();
}

// 16 gate-FMAs for TWO batches against one weight row: 4 LDS.128 + 16 FFMA2.
__device__ __forceinline__ void fma16x2_dual(unsigned long long aL[8],
                                             unsigned long long aH[8],
                                             const float* wrow, float vL, float vH) {
    unsigned long long vL2, vH2;
    asm("mov.b64 %0, {%1, %1};" : "=l"(vL2) : "r"(__float_as_uint(vL)));
    asm("mov.b64 %0, {%1, %1};" : "=l"(vH2) : "r"(__float_as_uint(vH)));
    #pragma unroll
    for (int g = 0; g < 4; ++g) {
        ulonglong2 w2 = *(const ulonglong2*)(wrow + g * 4);
        asm("fma.rn.f32x2 %0, %1, %2, %0;" : "+l"(aL[2*g])   : "l"(w2.x), "l"(vL2));
        asm("fma.rn.f32x2 %0, %1, %2, %0;" : "+l"(aH[2*g])   : "l"(w2.x), "l"(vH2));
        asm("fma.rn.f32x2 %0, %1, %2, %0;" : "+l"(aL[2*g+1]) : "l"(w2.y), "l"(vL2));
        asm("fma.rn.f32x2 %0, %1, %2, %0;" : "+l"(aH[2*g+1]) : "l"(w2.y), "l"(vH2));
    }
}

// One 4-k slab (one float4 of activations per batch) of a 16-gate GEMM.
__device__ __forceinline__ void gemm_4k(unsigned long long aL[8],
                                        unsigned long long aH[8],
                                        const float* rl, const float* rh,
                                        const float* wpc) {
    float4 al = *(const float4*)rl;
    float4 ah = *(const float4*)rh;
    fma16x2_dual(aL, aH, wpc +  0, al.x, ah.x);
    fma16x2_dual(aL, aH, wpc + 16, al.y, ah.y);
    fma16x2_dual(aL, aH, wpc + 32, al.z, ah.z);
    fma16x2_dual(aL, aH, wpc + 48, al.w, ah.w);
}

__device__ __forceinline__ float pk_lo(unsigned long long p) {
    return __uint_as_float((unsigned)(p & 0xffffffffu));
}
__device__ __forceinline__ float pk_hi(unsigned long long p) {
    return __uint_as_float((unsigned)(p >> 32));
}

// Vector dump of 16 packed partials (both batches) at stride-PST layout.
// Banking: lane b covers banks {20b..20b+3 mod 32}; 8-lane LDS.128 phases form a
// perfect bank partition -> conflict-free.
__device__ __forceinline__ void dump_partials(float* base, int oct, int blo, int bhi,
                                              const unsigned long long aL[8],
                                              const unsigned long long aH[8]) {
    float* dl = base + oct * PBLK + blo * PST;
    float* dh = base + oct * PBLK + bhi * PST;
    #pragma unroll
    for (int g = 0; g < 4; ++g) {
        *(float4*)(dl + g * 4) = make_float4(pk_lo(aL[2*g]), pk_hi(aL[2*g]),
                                             pk_lo(aL[2*g+1]), pk_hi(aL[2*g+1]));
        *(float4*)(dh + g * 4) = make_float4(pk_lo(aH[2*g]), pk_hi(aH[2*g]),
                                             pk_lo(aH[2*g+1]), pk_hi(aH[2*g+1]));
    }
}

// Vector gather+sum of 8 partial blocks for batch b into z[16].
__device__ __forceinline__ void sum_partials(float z[16], const float* base, int b,
                                             const float* bias) {
    #pragma unroll
    for (int q = 0; q < 16; q++) z[q] = bias[q];
    #pragma unroll
    for (int p = 0; p < 8; p++) {
        const float* s = base + p * PBLK + b * PST;
        #pragma unroll
        for (int g = 0; g < 4; ++g) {
            float4 v = *(const float4*)(s + g * 4);
            z[4*g]   += v.x;  z[4*g+1] += v.y;
            z[4*g+2] += v.z;  z[4*g+3] += v.w;
        }
    }
}

__global__ __launch_bounds__(NTHR, 1)
void cfc_kernel(const float* __restrict__ x,
                const float* __restrict__ lstm_Wi, const float* __restrict__ lstm_bi,
                const float* __restrict__ lstm_Wh,
                const float* __restrict__ bb_W,  const float* __restrict__ bb_b,
                const float* __restrict__ ff1_W, const float* __restrict__ ff1_b,
                const float* __restrict__ ff2_W, const float* __restrict__ ff2_b,
                const float* __restrict__ ta_W,  const float* __restrict__ ta_b,
                const float* __restrict__ tb_W,  const float* __restrict__ tb_b,
                const float* __restrict__ head_W, const float* __restrict__ head_b,
                float* __restrict__ out)
{
    extern __shared__ float sm[];
    float* wA2  = sm;                    // [576][16] gate weights, k-major layout
    float* wB   = wA2 + 576 * 16;        // [16][576] bb_W row block (row-major)
    float* wC2  = wB + 16 * 576;         // [128][16] ff1/ff2/ta/tb, k-major
    float* hW   = wC2 + 128 * 16;        // [2][512] head
    float* bA   = hW + 2 * 512;          // 16
    float* bB   = bA + 16;               // 16
    float* bC   = bB + 16;               // 16
    float* hb   = bC + 16;               // 16 (2 used)
    float* buf0 = hb + 16;               // [128][RS] streaming tile / partial scratch
    float* buf1 = buf0 + 128 * RS;       // [128][RS]

    const int tid = threadIdx.x;
    const int j   = blockIdx.x;          // owns hidden units 4j..4j+3; batch j for head
    const int b2  = tid & 63;            // batch pair: handles b2 and b2+64
    const int oct = tid >> 6;            // k-split 0..7 (uniform per warp)
    const int blo = b2, bhi = b2 + 64;
    const int bb0 = (j >> 3) * 8;        // phase-B batch block
    const int jj0 = (j & 7) * 16;        // phase-B bb_W row block

    // ---- One-time: resident weights into smem ----
    for (int idx = tid; idx < 576 * 16; idx += NTHR) {
        int k = idx >> 4, q = idx & 15;
        int grow = (q >> 2) * Hdim + 4 * j + (q & 3);   // gate g=q>>2, unit u=q&3
        wA2[idx] = (k < Idim) ? lstm_Wi[grow * Idim + k]
                              : lstm_Wh[grow * Hdim + (k - Idim)];
    }
    for (int idx = tid; idx < 16 * 576; idx += NTHR) {
        int r = idx / 576, k = idx - r * 576;
        wB[idx] = bb_W[(jj0 + r) * 576 + k];
    }
    for (int idx = tid; idx < 128 * 16; idx += NTHR) {
        int k = idx >> 4, r = idx & 15;
        const float* Wm = (r < 4) ? ff1_W : (r < 8) ? ff2_W : (r < 12) ? ta_W : tb_W;
        wC2[idx] = Wm[(4 * j + (r & 3)) * BBdim + k];
    }
    for (int idx = tid; idx < 2 * Hdim; idx += NTHR) hW[idx] = head_W[idx];
    if (tid < 16) {
        bA[tid] = lstm_bi[(tid >> 2) * Hdim + 4 * j + (tid & 3)];
        bB[tid] = bb_b[jj0 + tid];
        const float* bm = (tid < 4) ? ff1_b : (tid < 8) ? ff2_b : (tid < 12) ? ta_b : tb_b;
        bC[tid] = bm[4 * j + (tid & 3)];
    }
    if (tid < 2) hb[tid] = head_b[tid];
    __syncthreads();

    unsigned expect = 0;
    if (tid == 0) expect = g_bar_flag;   // race-free epoch base

    float cReg[4] = {0.f, 0.f, 0.f, 0.f};  // cell state for batch==tid (tid<128)

    for (int t = 0; t < Tdim; ++t) {
        // ============ Phase A: z = [x_t,h] @ W.T, LSTM update ============
        unsigned long long aLo[8], aHi[8];
        #pragma unroll
        for (int p = 0; p < 8; p++) { aLo[p] = 0ull; aHi[p] = 0ull; }

        // --- bar3(t-1) overlap window: stage x chunk 0, compute its 1st half ---
        {
            float4 st[4];
            #pragma unroll
            for (int r4 = 0; r4 < 4; r4++) {
                int idx4 = tid + NTHR * r4;
                int row = idx4 >> 4, c4 = idx4 & 15;
                st[r4] = *(const float4*)(x + (long)row * (Tdim * Idim) + t * Idim + c4 * 4);
            }
            #pragma unroll
            for (int r4 = 0; r4 < 4; r4++) {
                int idx4 = tid + NTHR * r4;
                int row = idx4 >> 4, c4 = idx4 & 15;
                *(float4*)(buf0 + row * RS + c4 * 4) = st[r4];
            }
        }
        __syncthreads();
        gemm_4k(aLo, aHi, buf0 + blo * RS + oct * 8, buf0 + bhi * RS + oct * 8,
                wA2 + (oct * 8) * 16);

        bar_wait(expect);    // bar3(t-1): h_{t-1} ready (no-op at t=0)

        if (t > 0) {
            float4 st[4];
            // prefetch h chunk 1 (g_h cols 0..63) while finishing chunk 0
            #pragma unroll
            for (int r4 = 0; r4 < 4; r4++) {
                int idx4 = tid + NTHR * r4;
                int row = idx4 >> 4, c4 = idx4 & 15;
                st[r4] = __ldcg((const float4*)(g_h + row * Hdim + c4 * 4));
            }
            gemm_4k(aLo, aHi, buf0 + blo * RS + oct * 8 + 4, buf0 + bhi * RS + oct * 8 + 4,
                    wA2 + (oct * 8 + 4) * 16);
            #pragma unroll
            for (int r4 = 0; r4 < 4; r4++) {
                int idx4 = tid + NTHR * r4;
                int row = idx4 >> 4, c4 = idx4 & 15;
                *(float4*)(buf1 + row * RS + c4 * 4) = st[r4];
            }
            __syncthreads();

            for (int c = 1; c < 9; ++c) {
                float4 st2[4];
                if (c < 8) {             // prefetch next h chunk (g_h cols c*64..)
                    #pragma unroll
                    for (int r4 = 0; r4 < 4; r4++) {
                        int idx4 = tid + NTHR * r4;
                        int row = idx4 >> 4, c4 = idx4 & 15;
                        st2[r4] = __ldcg((const float4*)(g_h + row * Hdim + c * 64 + c4 * 4));
                    }
                }
                {
                    const float* cb = (c & 1) ? buf1 : buf0;
                    const float* rl = cb + blo * RS + oct * 8;
                    const float* rh = cb + bhi * RS + oct * 8;
                    const float* wpc = wA2 + (c * 64 + oct * 8) * 16;
                    gemm_4k(aLo, aHi, rl, rh, wpc);
                    gemm_4k(aLo, aHi, rl + 4, rh + 4, wpc + 64);
                }
                if (c < 8) {
                    float* nb = ((c + 1) & 1) ? buf1 : buf0;
                    #pragma unroll
                    for (int r4 = 0; r4 < 4; r4++) {
                        int idx4 = tid + NTHR * r4;
                        int row = idx4 >> 4, c4 = idx4 & 15;
                        *(float4*)(nb + row * RS + c4 * 4) = st2[r4];
                    }
                }
                __syncthreads();
            }
        } else {
            gemm_4k(aLo, aHi, buf0 + blo * RS + oct * 8 + 4, buf0 + bhi * RS + oct * 8 + 4,
                    wA2 + (oct * 8 + 4) * 16);
            __syncthreads();             // protect buf0 before partial writes
        }

        // 8-way k-partial dump (vectorized, stride-PST)
        dump_partials(buf0, oct, blo, bhi, aLo, aHi);
        __syncthreads();
        if (tid < 128) {                 // thread tid finalizes batch tid
            float z[16];
            sum_partials(z, buf0, tid, bA);
            float hl[4];
            #pragma unroll
            for (int u = 0; u < 4; u++) {
                // z rows: [0..3]=i_, [4..7]=ig, [8..11]=fg, [12..15]=og
                float cn = cReg[u] * sigm(z[8 + u] + 1.0f) + tanhf(z[u]) * sigm(z[4 + u]);
                cReg[u] = cn;
                hl[u] = tanhf(cn) * sigm(z[12 + u]);
            }
            *(float4*)(g_hl + tid * Hdim + 4 * j) = make_float4(hl[0], hl[1], hl[2], hl[3]);
        }

        bar_arrive(expect);  // bar1: h_lstm posted

        // --- bar1 overlap window: phys head (t-1) + Phase-B x staging ---
        if (t > 0 && tid < 64) {
            int o = tid >> 5, l = tid & 31;
            float s = 0.f;
            for (int n = l; n < Hdim; n += 32)
                s += __ldcg(g_h + j * Hdim + n) * hW[o * Hdim + n];
            #pragma unroll
            for (int off = 16; off; off >>= 1) s += __shfl_down_sync(0xffffffffu, s, off);
            if (l == 0) out[((long)j * Tdim + (t - 1)) * Odim + o] = s + hb[o];
        }
        if (tid >= 128 && tid < 256) {   // B rows' x columns (no h_lstm dependency)
            int idx = tid - 128;
            int row = idx >> 4, col = (idx & 15) * 4;
            *(float4*)(buf0 + row * 576 + col) =
                *(const float4*)(x + (long)(bb0 + row) * (Tdim * Idim) + t * Idim + col);
        }

        bar_wait(expect);    // bar1: h_lstm ready

        // ============ Phase B: f = lecun_tanh([x_t,h_lstm] @ bbW.T + b) ============
        #pragma unroll
        for (int r2 = 0; r2 < 2; ++r2) {     // stage h_lstm columns (8 rows x 512 cols)
            int idx4 = tid + NTHR * r2;
            int row = idx4 >> 7, c4 = idx4 & 127;
            int col = 64 + c4 * 4;
            *(float4*)(buf0 + row * 576 + col) =
                __ldcg((const float4*)(g_hl + (bb0 + row) * Hdim + col - 64));
        }
        __syncthreads();
        float* bsc = buf0 + 128 * RS;    // 256-float reduction scratch (in buf1 area)
        {
            int w  = tid >> 5, l = tid & 31;
            int lb = w >> 1, kh = w & 1;     // local batch 0..7, k-half 0/1
            float a[16];
            #pragma unroll
            for (int r = 0; r < 16; r++) a[r] = 0.f;
            const float* xr = buf0 + lb * 576 + kh * 288;
            const float* wb = wB + kh * 288;
            for (int it = 0; it < 9; ++it) {
                int kk = it * 32 + l;
                float v = xr[kk];
                #pragma unroll
                for (int r = 0; r < 16; r++) a[r] = fmaf(v, wb[r * 576 + kk], a[r]);
            }
            #pragma unroll
            for (int r = 0; r < 16; r++) {
                #pragma unroll
                for (int off = 16; off; off >>= 1)
                    a[r] += __shfl_down_sync(0xffffffffu, a[r], off);
            }
            if (l == 0) {
                #pragma unroll
                for (int r = 0; r < 16; r++) bsc[(lb * 2 + kh) * 16 + r] = a[r];
            }
        }
        __syncthreads();
        if (tid < 128) {
            int lb = tid >> 4, r = tid & 15;
            float v = bsc[lb * 32 + r] + bsc[lb * 32 + 16 + r] + bB[r];
            g_f[(bb0 + lb) * BBdim + jj0 + r] = 1.7159f * tanhf(0.666f * v);
        }

        bar_arrive(expect);  // bar2: f posted
        bar_wait(expect);    // bar2: f ready

        // ============ Phase C: ff1/ff2/ta/tb, h_new ============
        #pragma unroll
        for (int r8 = 0; r8 < 8; ++r8) {     // stage full f (128x128) into buf0|buf1
            int idx4 = tid + NTHR * r8;
            int row = idx4 >> 5, c4 = idx4 & 31;
            float4 v = __ldcg((const float4*)(g_f + row * BBdim + c4 * 4));
            *(float4*)(((c4 < 16) ? buf0 : buf1) + row * RS + (c4 & 15) * 4) = v;
        }
        __syncthreads();
        unsigned long long cLo[8], cHi[8];
        #pragma unroll
        for (int p = 0; p < 8; p++) { cLo[p] = 0ull; cHi[p] = 0ull; }
        {
            const float* base = (oct >= 4) ? buf1 : buf0;
            const int coff = (oct & 3) * 16;
            const float* rl = base + blo * RS + coff;
            const float* rh = base + bhi * RS + coff;
            const float* wpc = wC2 + (oct * 16) * 16;
            #pragma unroll
            for (int s = 0; s < 4; ++s)
                gemm_4k(cLo, cHi, rl + s * 4, rh + s * 4, wpc + s * 64);
        }
        __syncthreads();
        dump_partials(buf0, oct, blo, bhi, cLo, cHi);
        __syncthreads();
        if (tid < 128) {
            float z[16];
            sum_partials(z, buf0, tid, bC);
            float hn[4];
            #pragma unroll
            for (int u = 0; u < 4; u++) {
                float f1 = tanhf(z[u]);                  // ff1
                float f2 = tanhf(z[4 + u]);              // ff2
                float ti = sigm(z[8 + u] + z[12 + u]);   // sigmoid(ta*1 + tb)
                hn[u] = f1 * (1.f - ti) + ti * f2;
            }
            *(float4*)(g_h + tid * Hdim + 4 * j) = make_float4(hn[0], hn[1], hn[2], hn[3]);
        }

        bar_arrive(expect);  // bar3: h_t posted (waited at top of next iteration)
    }

    bar_wait(expect);        // final bar3: h_{T-1} ready everywhere

    // ---- Epilogue: phys for t = T-1, and last_h ----
    if (tid < 64) {
        int o = tid >> 5, l = tid & 31;
        float s = 0.f;
        for (int n = l; n < Hdim; n += 32)
            s += __ldcg(g_h + j * Hdim + n) * hW[o * Hdim + n];
        #pragma unroll
        for (int off = 16; off; off >>= 1) s += __shfl_down_sync(0xffffffffu, s, off);
        if (l == 0) out[((long)j * Tdim + (Tdim - 1)) * Odim + o] = s + hb[o];
    }
    float* out_lh = out + (long)Bdim * Tdim * Odim;
    for (int i4 = tid; i4 < Hdim / 4; i4 += NTHR) {
        float4 v = __ldcg((const float4*)(g_h + j * Hdim + i4 * 4));
        *(float4*)(out_lh + j * Hdim + i4 * 4) = v;
    }
}

extern "C" void kernel_launch(void* const* d_in, const int* in_sizes, int n_in,
                              void* d_out, int out_size) {
    (void)in_sizes; (void)n_in; (void)out_size;
    const int SMEM_BYTES = (576 * 16 + 16 * 576 + 128 * 16 + 2 * 512 + 64
                            + BUFFL) * 4;   // 168,192 B
    cudaFuncSetAttribute(cfc_kernel, cudaFuncAttributeMaxDynamicSharedMemorySize, SMEM_BYTES);
    cfc_kernel<<<NCTA, NTHR, SMEM_BYTES>>>(
        (const float*)d_in[0],  (const float*)d_in[1],  (const float*)d_in[2],
        (const float*)d_in[3],  (const float*)d_in[4],  (const float*)d_in[5],
        (const float*)d_in[6],  (const float*)d_in[7],  (const float*)d_in[8],
        (const float*)d_in[9],  (const float*)d_in[10], (const float*)d_in[11],
        (const float*)d_in[12], (const float*)d_in[13], (const float*)d_in[14],
        (const float*)d_in[15], (float*)d_out);
}

// round 13
// speedup vs baseline: 1.0965x; 1.0675x over previous
#include <cuda_runtime.h>

// Problem shape (fixed by reference)
#define Bdim  128
#define Tdim  1024
#define Idim  64
#define Hdim  512
#define BBdim 128
#define Odim  2

#define NCTA 128   // one CTA per 4 hidden units; also CTA j <-> batch j for phys head
#define NTHR 512   // 16 warps

#define RS    68           // buffer row stride (17 float4s -> conflict-free LDS.128)
#define PST   20           // partial row stride (5 float4s, conflict-free vector r/w)
#define PBLK  (128 * PST)  // one partial block: 2560 floats; 8 blocks = 20480
#define BUFFL 20480        // buffer region floats (covers 2*128*RS=17408 and partials)

// Cross-CTA state (persistent kernel; no allocations allowed)
__device__ float g_h[Bdim * Hdim];      // h_{t-1} / h_t
__device__ float g_hl[Bdim * Hdim];     // h_lstm at current step
__device__ float g_f[Bdim * BBdim];     // backbone activations
__device__ unsigned g_bar_count;
__device__ volatile unsigned g_bar_flag;

__device__ __forceinline__ float sigm(float v) { return 1.0f / (1.0f + expf(-v)); }

// Proven atomic barrier, split into arrive / wait (R8).
__device__ __forceinline__ void bar_arrive(unsigned &expect) {
    __syncthreads();
    expect += 1u;
    if (threadIdx.x == 0) {
        __threadfence();
        if (atomicAdd(&g_bar_count, 1u) == NCTA - 1) {
            g_bar_count = 0;
            __threadfence();
            g_bar_flag = expect;
        }
    }
}
__device__ __forceinline__ void bar_wait(unsigned expect) {
    if (threadIdx.x == 0) {
        while (g_bar_flag != expect) { }
    }
    __syncthreads();
}

// 16 gate-FMAs for TWO batches against one weight row: 4 LDS.128 + 16 FFMA2.
__device__ __forceinline__ void fma16x2_dual(unsigned long long aL[8],
                                             unsigned long long aH[8],
                                             const float* wrow, float vL, float vH) {
    unsigned long long vL2, vH2;
    asm("mov.b64 %0, {%1, %1};" : "=l"(vL2) : "r"(__float_as_uint(vL)));
    asm("mov.b64 %0, {%1, %1};" : "=l"(vH2) : "r"(__float_as_uint(vH)));
    #pragma unroll
    for (int g = 0; g < 4; ++g) {
        ulonglong2 w2 = *(const ulonglong2*)(wrow + g * 4);
        asm("fma.rn.f32x2 %0, %1, %2, %0;" : "+l"(aL[2*g])   : "l"(w2.x), "l"(vL2));
        asm("fma.rn.f32x2 %0, %1, %2, %0;" : "+l"(aH[2*g])   : "l"(w2.x), "l"(vH2));
        asm("fma.rn.f32x2 %0, %1, %2, %0;" : "+l"(aL[2*g+1]) : "l"(w2.y), "l"(vL2));
        asm("fma.rn.f32x2 %0, %1, %2, %0;" : "+l"(aH[2*g+1]) : "l"(w2.y), "l"(vH2));
    }
}

// One 4-k slab (one float4 of activations per batch) of a 16-gate GEMM.
__device__ __forceinline__ void gemm_4k(unsigned long long aL[8],
                                        unsigned long long aH[8],
                                        const float* rl, const float* rh,
                                        const float* wpc) {
    float4 al = *(const float4*)rl;
    float4 ah = *(const float4*)rh;
    fma16x2_dual(aL, aH, wpc +  0, al.x, ah.x);
    fma16x2_dual(aL, aH, wpc + 16, al.y, ah.y);
    fma16x2_dual(aL, aH, wpc + 32, al.z, ah.z);
    fma16x2_dual(aL, aH, wpc + 48, al.w, ah.w);
}

__device__ __forceinline__ float pk_lo(unsigned long long p) {
    return __uint_as_float((unsigned)(p & 0xffffffffu));
}
__device__ __forceinline__ float pk_hi(unsigned long long p) {
    return __uint_as_float((unsigned)(p >> 32));
}

// Vector dump of 16 packed partials (both batches) at stride-PST layout.
// Banking: lane b covers banks {20b..20b+3 mod 32}; 8-lane LDS.128 phases form a
// perfect bank partition -> conflict-free.
__device__ __forceinline__ void dump_partials(float* base, int oct, int blo, int bhi,
                                              const unsigned long long aL[8],
                                              const unsigned long long aH[8]) {
    float* dl = base + oct * PBLK + blo * PST;
    float* dh = base + oct * PBLK + bhi * PST;
    #pragma unroll
    for (int g = 0; g < 4; ++g) {
        *(float4*)(dl + g * 4) = make_float4(pk_lo(aL[2*g]), pk_hi(aL[2*g]),
                                             pk_lo(aL[2*g+1]), pk_hi(aL[2*g+1]));
        *(float4*)(dh + g * 4) = make_float4(pk_lo(aH[2*g]), pk_hi(aH[2*g]),
                                             pk_lo(aH[2*g+1]), pk_hi(aH[2*g+1]));
    }
}

// Spread finalize: thread (b,u) sums its 4 gate partials across the 8 k-blocks.
// Scalar loads; banks (20b+u+off)%32 are all-distinct within a warp per load.
__device__ __forceinline__ void sum4_spread(float z[4], const float* base, int b,
                                            int u, const float* bias) {
    z[0] = bias[u];  z[1] = bias[4 + u];  z[2] = bias[8 + u];  z[3] = bias[12 + u];
    #pragma unroll
    for (int p = 0; p < 8; p++) {
        const float* s = base + p * PBLK + b * PST;
        z[0] += s[u];  z[1] += s[u + 4];  z[2] += s[u + 8];  z[3] += s[u + 12];
    }
}

__global__ __launch_bounds__(NTHR, 1)
void cfc_kernel(const float* __restrict__ x,
                const float* __restrict__ lstm_Wi, const float* __restrict__ lstm_bi,
                const float* __restrict__ lstm_Wh,
                const float* __restrict__ bb_W,  const float* __restrict__ bb_b,
                const float* __restrict__ ff1_W, const float* __restrict__ ff1_b,
                const float* __restrict__ ff2_W, const float* __restrict__ ff2_b,
                const float* __restrict__ ta_W,  const float* __restrict__ ta_b,
                const float* __restrict__ tb_W,  const float* __restrict__ tb_b,
                const float* __restrict__ head_W, const float* __restrict__ head_b,
                float* __restrict__ out)
{
    extern __shared__ float sm[];
    float* wA2  = sm;                    // [576][16] gate weights, k-major layout
    float* wB   = wA2 + 576 * 16;        // [16][576] bb_W row block (row-major)
    float* wC2  = wB + 16 * 576;         // [128][16] ff1/ff2/ta/tb, k-major
    float* hW   = wC2 + 128 * 16;        // [2][512] head
    float* bA   = hW + 2 * 512;          // 16
    float* bB   = bA + 16;               // 16
    float* bC   = bB + 16;               // 16
    float* hb   = bC + 16;               // 16 (2 used)
    float* buf0 = hb + 16;               // [128][RS] streaming tile / partial scratch
    float* buf1 = buf0 + 128 * RS;       // [128][RS]

    const int tid = threadIdx.x;
    const int j   = blockIdx.x;          // owns hidden units 4j..4j+3; batch j for head
    const int b2  = tid & 63;            // batch pair: handles b2 and b2+64
    const int oct = tid >> 6;            // k-split 0..7 (uniform per warp)
    const int blo = b2, bhi = b2 + 64;
    const int fb  = tid >> 2;            // finalize: batch 0..127
    const int fu  = tid & 3;             // finalize: unit 0..3
    const int bb0 = (j >> 3) * 8;        // phase-B batch block
    const int jj0 = (j & 7) * 16;        // phase-B bb_W row block

    // ---- One-time: resident weights into smem ----
    for (int idx = tid; idx < 576 * 16; idx += NTHR) {
        int k = idx >> 4, q = idx & 15;
        int grow = (q >> 2) * Hdim + 4 * j + (q & 3);   // gate g=q>>2, unit u=q&3
        wA2[idx] = (k < Idim) ? lstm_Wi[grow * Idim + k]
                              : lstm_Wh[grow * Hdim + (k - Idim)];
    }
    for (int idx = tid; idx < 16 * 576; idx += NTHR) {
        int r = idx / 576, k = idx - r * 576;
        wB[idx] = bb_W[(jj0 + r) * 576 + k];
    }
    for (int idx = tid; idx < 128 * 16; idx += NTHR) {
        int k = idx >> 4, r = idx & 15;
        const float* Wm = (r < 4) ? ff1_W : (r < 8) ? ff2_W : (r < 12) ? ta_W : tb_W;
        wC2[idx] = Wm[(4 * j + (r & 3)) * BBdim + k];
    }
    for (int idx = tid; idx < 2 * Hdim; idx += NTHR) hW[idx] = head_W[idx];
    if (tid < 16) {
        bA[tid] = lstm_bi[(tid >> 2) * Hdim + 4 * j + (tid & 3)];
        bB[tid] = bb_b[jj0 + tid];
        const float* bm = (tid < 4) ? ff1_b : (tid < 8) ? ff2_b : (tid < 12) ? ta_b : tb_b;
        bC[tid] = bm[4 * j + (tid & 3)];
    }
    if (tid < 2) hb[tid] = head_b[tid];
    __syncthreads();

    unsigned expect = 0;
    if (tid == 0) expect = g_bar_flag;   // race-free epoch base

    float cReg = 0.f;   // cell state for (batch fb, unit 4j+fu); fixed owner all steps

    for (int t = 0; t < Tdim; ++t) {
        // ============ Phase A: z = [x_t,h] @ W.T, LSTM update ============
        unsigned long long aLo[8], aHi[8];
        #pragma unroll
        for (int p = 0; p < 8; p++) { aLo[p] = 0ull; aHi[p] = 0ull; }

        // --- bar3(t-1) overlap window: stage x chunk 0, compute its 1st half ---
        {
            float4 st[4];
            #pragma unroll
            for (int r4 = 0; r4 < 4; r4++) {
                int idx4 = tid + NTHR * r4;
                int row = idx4 >> 4, c4 = idx4 & 15;
                st[r4] = *(const float4*)(x + (long)row * (Tdim * Idim) + t * Idim + c4 * 4);
            }
            #pragma unroll
            for (int r4 = 0; r4 < 4; r4++) {
                int idx4 = tid + NTHR * r4;
                int row = idx4 >> 4, c4 = idx4 & 15;
                *(float4*)(buf0 + row * RS + c4 * 4) = st[r4];
            }
        }
        __syncthreads();
        gemm_4k(aLo, aHi, buf0 + blo * RS + oct * 8, buf0 + bhi * RS + oct * 8,
                wA2 + (oct * 8) * 16);

        bar_wait(expect);    // bar3(t-1): h_{t-1} ready (no-op at t=0)

        if (t > 0) {
            float4 st[4];
            // prefetch h chunk 1 (g_h cols 0..63) while finishing chunk 0
            #pragma unroll
            for (int r4 = 0; r4 < 4; r4++) {
                int idx4 = tid + NTHR * r4;
                int row = idx4 >> 4, c4 = idx4 & 15;
                st[r4] = __ldcg((const float4*)(g_h + row * Hdim + c4 * 4));
            }
            gemm_4k(aLo, aHi, buf0 + blo * RS + oct * 8 + 4, buf0 + bhi * RS + oct * 8 + 4,
                    wA2 + (oct * 8 + 4) * 16);
            #pragma unroll
            for (int r4 = 0; r4 < 4; r4++) {
                int idx4 = tid + NTHR * r4;
                int row = idx4 >> 4, c4 = idx4 & 15;
                *(float4*)(buf1 + row * RS + c4 * 4) = st[r4];
            }
            __syncthreads();

            for (int c = 1; c < 9; ++c) {
                float4 st2[4];
                if (c < 8) {             // prefetch next h chunk (g_h cols c*64..)
                    #pragma unroll
                    for (int r4 = 0; r4 < 4; r4++) {
                        int idx4 = tid + NTHR * r4;
                        int row = idx4 >> 4, c4 = idx4 & 15;
                        st2[r4] = __ldcg((const float4*)(g_h + row * Hdim + c * 64 + c4 * 4));
                    }
                }
                {
                    const float* cb = (c & 1) ? buf1 : buf0;
                    const float* rl = cb + blo * RS + oct * 8;
                    const float* rh = cb + bhi * RS + oct * 8;
                    const float* wpc = wA2 + (c * 64 + oct * 8) * 16;
                    gemm_4k(aLo, aHi, rl, rh, wpc);
                    gemm_4k(aLo, aHi, rl + 4, rh + 4, wpc + 64);
                }
                if (c < 8) {
                    float* nb = ((c + 1) & 1) ? buf1 : buf0;
                    #pragma unroll
                    for (int r4 = 0; r4 < 4; r4++) {
                        int idx4 = tid + NTHR * r4;
                        int row = idx4 >> 4, c4 = idx4 & 15;
                        *(float4*)(nb + row * RS + c4 * 4) = st2[r4];
                    }
                }
                __syncthreads();
            }
        } else {
            gemm_4k(aLo, aHi, buf0 + blo * RS + oct * 8 + 4, buf0 + bhi * RS + oct * 8 + 4,
                    wA2 + (oct * 8 + 4) * 16);
            __syncthreads();             // protect buf0 before partial writes
        }

        // 8-way k-partial dump (vectorized, stride-PST)
        dump_partials(buf0, oct, blo, bhi, aLo, aHi);
        __syncthreads();
        {   // spread LSTM finalize: all 512 threads, one (batch,unit) each
            float z[4];                  // z[0]=i_, z[1]=ig, z[2]=fg, z[3]=og
            sum4_spread(z, buf0, fb, fu, bA);
            float cn = cReg * sigm(z[2] + 1.0f) + tanhf(z[0]) * sigm(z[1]);
            cReg = cn;
            g_hl[fb * Hdim + 4 * j + fu] = tanhf(cn) * sigm(z[3]);
        }

        bar_arrive(expect);  // bar1: h_lstm posted

        // --- bar1 overlap window: phys head (t-1) + Phase-B x staging ---
        if (t > 0 && tid < 64) {
            int o = tid >> 5, l = tid & 31;
            float s = 0.f;
            for (int n = l; n < Hdim; n += 32)
                s += __ldcg(g_h + j * Hdim + n) * hW[o * Hdim + n];
            #pragma unroll
            for (int off = 16; off; off >>= 1) s += __shfl_down_sync(0xffffffffu, s, off);
            if (l == 0) out[((long)j * Tdim + (t - 1)) * Odim + o] = s + hb[o];
        }
        if (tid >= 128 && tid < 256) {   // B rows' x columns (no h_lstm dependency)
            int idx = tid - 128;
            int row = idx >> 4, col = (idx & 15) * 4;
            *(float4*)(buf0 + row * 576 + col) =
                *(const float4*)(x + (long)(bb0 + row) * (Tdim * Idim) + t * Idim + col);
        }

        bar_wait(expect);    // bar1: h_lstm ready

        // ============ Phase B: f = lecun_tanh([x_t,h_lstm] @ bbW.T + b) ============
        #pragma unroll
        for (int r2 = 0; r2 < 2; ++r2) {     // stage h_lstm columns (8 rows x 512 cols)
            int idx4 = tid + NTHR * r2;
            int row = idx4 >> 7, c4 = idx4 & 127;
            int col = 64 + c4 * 4;
            *(float4*)(buf0 + row * 576 + col) =
                __ldcg((const float4*)(g_hl + (bb0 + row) * Hdim + col - 64));
        }
        __syncthreads();
        float* bsc = buf0 + 128 * RS;    // 256-float reduction scratch (in buf1 area)
        {
            int w  = tid >> 5, l = tid & 31;
            int lb = w >> 1, kh = w & 1;     // local batch 0..7, k-half 0/1
            float a[16];
            #pragma unroll
            for (int r = 0; r < 16; r++) a[r] = 0.f;
            const float* xr = buf0 + lb * 576 + kh * 288;
            const float* wb = wB + kh * 288;
            for (int it = 0; it < 9; ++it) {
                int kk = it * 32 + l;
                float v = xr[kk];
                #pragma unroll
                for (int r = 0; r < 16; r++) a[r] = fmaf(v, wb[r * 576 + kk], a[r]);
            }
            #pragma unroll
            for (int r = 0; r < 16; r++) {
                #pragma unroll
                for (int off = 16; off; off >>= 1)
                    a[r] += __shfl_down_sync(0xffffffffu, a[r], off);
            }
            if (l == 0) {
                #pragma unroll
                for (int r = 0; r < 16; r++) bsc[(lb * 2 + kh) * 16 + r] = a[r];
            }
        }
        __syncthreads();
        if (tid < 128) {
            int lb = tid >> 4, r = tid & 15;
            float v = bsc[lb * 32 + r] + bsc[lb * 32 + 16 + r] + bB[r];
            g_f[(bb0 + lb) * BBdim + jj0 + r] = 1.7159f * tanhf(0.666f * v);
        }

        bar_arrive(expect);  // bar2: f posted
        bar_wait(expect);    // bar2: f ready

        // ============ Phase C: ff1/ff2/ta/tb, h_new ============
        #pragma unroll
        for (int r8 = 0; r8 < 8; ++r8) {     // stage full f (128x128) into buf0|buf1
            int idx4 = tid + NTHR * r8;
            int row = idx4 >> 5, c4 = idx4 & 31;
            float4 v = __ldcg((const float4*)(g_f + row * BBdim + c4 * 4));
            *(float4*)(((c4 < 16) ? buf0 : buf1) + row * RS + (c4 & 15) * 4) = v;
        }
        __syncthreads();
        unsigned long long cLo[8], cHi[8];
        #pragma unroll
        for (int p = 0; p < 8; p++) { cLo[p] = 0ull; cHi[p] = 0ull; }
        {
            const float* base = (oct >= 4) ? buf1 : buf0;
            const int coff = (oct & 3) * 16;
            const float* rl = base + blo * RS + coff;
            const float* rh = base + bhi * RS + coff;
            const float* wpc = wC2 + (oct * 16) * 16;
            #pragma unroll
            for (int s = 0; s < 4; ++s)
                gemm_4k(cLo, cHi, rl + s * 4, rh + s * 4, wpc + s * 64);
        }
        __syncthreads();
        dump_partials(buf0, oct, blo, bhi, cLo, cHi);
        __syncthreads();
        {   // spread CfC finalize: all 512 threads, one (batch,unit) each
            float z[4];                  // z[0]=ff1, z[1]=ff2, z[2]=ta, z[3]=tb
            sum4_spread(z, buf0, fb, fu, bC);
            float f1 = tanhf(z[0]);
            float f2 = tanhf(z[1]);
            float ti = sigm(z[2] + z[3]);    // sigmoid(ta*1 + tb)
            g_h[fb * Hdim + 4 * j + fu] = f1 * (1.f - ti) + ti * f2;
        }

        bar_arrive(expect);  // bar3: h_t posted (waited at top of next iteration)
    }

    bar_wait(expect);        // final bar3: h_{T-1} ready everywhere

    // ---- Epilogue: phys for t = T-1, and last_h ----
    if (tid < 64) {
        int o = tid >> 5, l = tid & 31;
        float s = 0.f;
        for (int n = l; n < Hdim; n += 32)
            s += __ldcg(g_h + j * Hdim + n) * hW[o * Hdim + n];
        #pragma unroll
        for (int off = 16; off; off >>= 1) s += __shfl_down_sync(0xffffffffu, s, off);
        if (l == 0) out[((long)j * Tdim + (Tdim - 1)) * Odim + o] = s + hb[o];
    }
    float* out_lh = out + (long)Bdim * Tdim * Odim;
    for (int i4 = tid; i4 < Hdim / 4; i4 += NTHR) {
        float4 v = __ldcg((const float4*)(g_h + j * Hdim + i4 * 4));
        *(float4*)(out_lh + j * Hdim + i4 * 4) = v;
    }
}

extern "C" void kernel_launch(void* const* d_in, const int* in_sizes, int n_in,
                              void* d_out, int out_size) {
    (void)in_sizes; (void)n_in; (void)out_size;
    const int SMEM_BYTES = (576 * 16 + 16 * 576 + 128 * 16 + 2 * 512 + 64
                            + BUFFL) * 4;   // 168,192 B
    cudaFuncSetAttribute(cfc_kernel, cudaFuncAttributeMaxDynamicSharedMemorySize, SMEM_BYTES);
    cfc_kernel<<<NCTA, NTHR, SMEM_BYTES>>>(
        (const float*)d_in[0],  (const float*)d_in[1],  (const float*)d_in[2],
        (const float*)d_in[3],  (const float*)d_in[4],  (const float*)d_in[5],
        (const float*)d_in[6],  (const float*)d_in[7],  (const float*)d_in[8],
        (const float*)d_in[9],  (const float*)d_in[10], (const float*)d_in[11],
        (const float*)d_in[12], (const float*)d_in[13], (const float*)d_in[14],
        (const float*)d_in[15], (float*)d_out);
}